// round 12
// baseline (speedup 1.0000x reference)
#include <cuda_runtime.h>
#include <cuda_fp16.h>
#include <cstdint>

#define N_PTS 32768
#define M_PTS 8192
#define D_DIM 64
#define BM 128
#define BN 128
#define NTILES (M_PTS / BN)          // 64
#define NBLOCKS (N_PTS / BM)         // 256

#define QSCALE 24.0f
#define EPI_K  (-2.0f / (QSCALE * QSCALE))

// dynamic smem layout (bytes)
#define OFF_XQ     0                 // 8192  (128 x 64 s8, paired-row swizzle)
#define OFF_Y      8192              // 3 * 8192 (triple-buffered y)
#define OFF_BS     32768             // 3 * 128 * 4
#define OFF_X2S    34304             // 128 * 4
#define OFF_ROWRED 34816             // 4 * 128 * 4
#define OFF_RED    36864             // 16
#define SMEM_TOTAL 36880

__device__ int8_t g_yq[M_PTS * D_DIM];
__device__ float g_b[M_PTS];
__device__ float g_partials[NBLOCKS];

__device__ __forceinline__ uint32_t smem_u32(const void* p) {
    uint32_t a;
    asm("{ .reg .u64 t; cvta.to.shared.u64 t, %1; cvt.u32.u64 %0, t; }" : "=r"(a) : "l"(p));
    return a;
}

// quantize 4 floats -> packed s8x4
__device__ __forceinline__ uint32_t q4(float4 v) {
    int a = __float2int_rn(fminf(fmaxf(v.x * QSCALE, -127.f), 127.f));
    int b = __float2int_rn(fminf(fmaxf(v.y * QSCALE, -127.f), 127.f));
    int c = __float2int_rn(fminf(fmaxf(v.z * QSCALE, -127.f), 127.f));
    int d = __float2int_rn(fminf(fmaxf(v.w * QSCALE, -127.f), 127.f));
    return (uint32_t)(a & 255) | ((uint32_t)(b & 255) << 8) |
           ((uint32_t)(c & 255) << 16) | ((uint32_t)(d & 255) << 24);
}

// paired-row swizzled smem byte offset for (row, kb16) ; kb16 = 16B chunk 0..3
__device__ __forceinline__ uint32_t sw_addr(int row, int kb) {
    return (uint32_t)((row >> 1) * 128 +
           (((((row & 1) << 2) | kb) ^ ((row >> 1) & 7)) << 4));
}

#define CP_ASYNC16(s, g) \
    asm volatile("cp.async.cg.shared.global [%0], [%1], 16;" :: "r"(s), "l"(g))
#define CP_COMMIT()  asm volatile("cp.async.commit_group;" ::: "memory")
#define CP_WAIT(N)   asm volatile("cp.async.wait_group %0;" :: "n"(N) : "memory")

#define LDSM4(r, addr) \
    asm volatile("ldmatrix.sync.aligned.m8n8.x4.shared.b16 {%0,%1,%2,%3}, [%4];" \
                 : "=r"((r)[0]), "=r"((r)[1]), "=r"((r)[2]), "=r"((r)[3]) : "r"(addr))

#define MMA_S8(c, a, b0, b1) \
    asm volatile("mma.sync.aligned.m16n8k32.row.col.s32.s8.s8.s32 " \
                 "{%0,%1,%2,%3},{%4,%5,%6,%7},{%8,%9},{%0,%1,%2,%3};" \
                 : "+r"((c)[0]), "+r"((c)[1]), "+r"((c)[2]), "+r"((c)[3]) \
                 : "r"((a)[0]), "r"((a)[1]), "r"((a)[2]), "r"((a)[3]), "r"(b0), "r"(b1))

// ---------------------------------------------------------------------------
// Prep: s8 quantization of y; b_j = ||y_j||^2 - psi_j (fp32, exact)
// ---------------------------------------------------------------------------
__global__ void prep_y_kernel(const float* __restrict__ y,
                              const float* __restrict__ psi) {
    int t = blockIdx.x * blockDim.x + threadIdx.x;   // 0 .. M*D/16-1 (32768)
    {
        const float4* src = (const float4*)(y + (size_t)t * 16);
        uint4 o;
        o.x = q4(src[0]); o.y = q4(src[1]); o.z = q4(src[2]); o.w = q4(src[3]);
        ((uint4*)g_yq)[t] = o;
    }
    if (t < M_PTS) {
        const float4* yr = (const float4*)(y + (size_t)t * D_DIM);
        float s = 0.f;
#pragma unroll
        for (int q = 0; q < 16; q++) {
            float4 w = yr[q];
            s = fmaf(w.x, w.x, s); s = fmaf(w.y, w.y, s);
            s = fmaf(w.z, w.z, s); s = fmaf(w.w, w.w, s);
        }
        g_b[t] = s - psi[t];
    }
}

// ---------------------------------------------------------------------------
// Main: int8 m16n8k32 mma (4096 MAC/instr), fused fp32 min-epilogue.
// 8 warps: wm = w>>2 (2), wn = w&3 (4); warp tile 64 x 32, two 32-row chunks,
// B fragments live across chunks. Triple-buffered y, one barrier per tile.
// ---------------------------------------------------------------------------
__global__ __launch_bounds__(256, 2)
void semidual_mma_kernel(const float* __restrict__ x) {
    extern __shared__ char smem[];
    const uint32_t sb = smem_u32(smem);
    const int tid  = threadIdx.x;
    const int lane = tid & 31;
    const int w    = tid >> 5;
    const int wm   = w >> 2;
    const int wn   = w & 3;
    const int i0   = blockIdx.x * BM;

    // cp.async one [128 x 64] s8 y-tile with paired-row swizzle (2 chunks/thr)
    auto tile_cp = [&](int row0, uint32_t soff) {
        const char* gp = (const char*)(g_yq + (size_t)row0 * D_DIM);
#pragma unroll
        for (int it = 0; it < 2; it++) {
            int c   = it * 256 + tid;        // 0..511
            int row = c >> 2, kb = c & 3;
            CP_ASYNC16(sb + soff + sw_addr(row, kb), gp + (size_t)c * 16);
        }
    };

    // quantize x tile fp32 -> s8 directly into swizzled smem
    {
#pragma unroll
        for (int it = 0; it < 2; it++) {
            int c   = it * 256 + tid;        // 0..511
            int row = c >> 2, kb = c & 3;
            const float4* src = (const float4*)(x + (size_t)(i0 + row) * D_DIM + kb * 16);
            uint4 o;
            o.x = q4(src[0]); o.y = q4(src[1]); o.z = q4(src[2]); o.w = q4(src[3]);
            *(uint4*)(smem + OFF_XQ + sw_addr(row, kb)) = o;
        }
    }

    // prologue: y tiles 0 and 1; bs slots 0,1; x2 (exact fp32)
    tile_cp(0, OFF_Y);
    CP_COMMIT();
    tile_cp(BN, OFF_Y + 8192);
    CP_COMMIT();
    if (tid < BM) {
        ((float*)(smem + OFF_BS))[tid]      = g_b[tid];
        ((float*)(smem + OFF_BS))[BN + tid] = g_b[BN + tid];
        const float4* xr = (const float4*)(x + (size_t)(i0 + tid) * D_DIM);
        float x2 = 0.f;
#pragma unroll
        for (int q = 0; q < 16; q++) {
            float4 v = xr[q];
            x2 = fmaf(v.x, v.x, x2); x2 = fmaf(v.y, v.y, x2);
            x2 = fmaf(v.z, v.z, x2); x2 = fmaf(v.w, v.w, x2);
        }
        ((float*)(smem + OFF_X2S))[tid] = x2;
    }

    // per-lane ldmatrix row/chunk bases
    const int rA  = (lane & 7) | (((lane >> 3) & 1) << 3);  // A row offset 0..15
    const int kbA = lane >> 4;                              // A 16B-chunk sel 0/1
    const int rB  = (lane & 7) | (((lane >> 4) & 1) << 3);  // B row offset 0..15
    const int kbB = (lane >> 3) & 1;                        // B 16B-chunk sel 0/1
    const int j0b = wn * 32 + (lane & 3) * 2;

    float rmin[8];
#pragma unroll
    for (int r = 0; r < 8; r++) rmin[r] = 3.4e38f;

    for (int t = 0; t < NTILES; t++) {
        const int b = t % 3;
        if (t + 1 < NTILES) {
            const int nb = (t + 1) % 3;
            tile_cp((t + 1) * BN, OFF_Y + nb * 8192);
            CP_COMMIT();
            if (tid < BN)
                ((float*)(smem + OFF_BS))[nb * BN + tid] = g_b[(t + 1) * BN + tid];
            CP_WAIT(1);
        } else {
            CP_WAIT(0);
        }
        __syncthreads();

        const uint32_t yb  = sb + OFF_Y + b * 8192;
        const uint32_t axq = sb + OFF_XQ;
        const float* bsf = (const float*)(smem + OFF_BS) + b * BN;

        // load all B fragments for this tile: bf[np][kc][4]
        uint32_t bf[2][2][4];
#pragma unroll
        for (int np = 0; np < 2; np++)
#pragma unroll
            for (int kc = 0; kc < 2; kc++) {
                int j  = wn * 32 + np * 16 + rB;
                int kb = kc * 2 + kbB;
                LDSM4(bf[np][kc], yb + sw_addr(j, kb));
            }

#pragma unroll
        for (int mtc = 0; mtc < 2; mtc++) {
            int c[2][4][4];
#pragma unroll
            for (int mt = 0; mt < 2; mt++)
#pragma unroll
                for (int nt = 0; nt < 4; nt++)
#pragma unroll
                    for (int q = 0; q < 4; q++) c[mt][nt][q] = 0;

#pragma unroll
            for (int kc = 0; kc < 2; kc++) {
                uint32_t a[2][4];
#pragma unroll
                for (int mt = 0; mt < 2; mt++) {
                    int row = wm * 64 + (mtc * 2 + mt) * 16 + rA;
                    int kb  = kc * 2 + kbA;
                    LDSM4(a[mt], axq + sw_addr(row, kb));
                }
#pragma unroll
                for (int mt = 0; mt < 2; mt++)
#pragma unroll
                    for (int nt = 0; nt < 4; nt++)
                        MMA_S8(c[mt][nt], a[mt],
                               bf[nt >> 1][kc][(nt & 1) * 2],
                               bf[nt >> 1][kc][(nt & 1) * 2 + 1]);
            }

            // fold chunk into rmin: v = b_j - (2/s^2) * dot_int
#pragma unroll
            for (int nt = 0; nt < 4; nt++) {
                const float b0 = bsf[j0b + nt * 8];
                const float b1 = bsf[j0b + nt * 8 + 1];
#pragma unroll
                for (int mt = 0; mt < 2; mt++) {
                    const int mi = mtc * 2 + mt;
                    float v0 = fminf(fmaf(EPI_K, (float)c[mt][nt][0], b0),
                                     fmaf(EPI_K, (float)c[mt][nt][1], b1));
                    float v1 = fminf(fmaf(EPI_K, (float)c[mt][nt][2], b0),
                                     fmaf(EPI_K, (float)c[mt][nt][3], b1));
                    rmin[mi * 2]     = fminf(rmin[mi * 2], v0);
                    rmin[mi * 2 + 1] = fminf(rmin[mi * 2 + 1], v1);
                }
            }
        }
    }

    // min across the 4 j-lanes of each row group
#pragma unroll
    for (int r = 0; r < 8; r++) {
        rmin[r] = fminf(rmin[r], __shfl_xor_sync(0xffffffffu, rmin[r], 1));
        rmin[r] = fminf(rmin[r], __shfl_xor_sync(0xffffffffu, rmin[r], 2));
    }
    float* rowred = (float*)(smem + OFF_ROWRED);
    __syncthreads();
    if ((lane & 3) == 0) {
        const int g = lane >> 2;
#pragma unroll
        for (int mt = 0; mt < 4; mt++) {
            const int r0 = wm * 64 + mt * 16 + g;
            rowred[wn * BM + r0]     = rmin[mt * 2];
            rowred[wn * BM + r0 + 8] = rmin[mt * 2 + 1];
        }
    }
    __syncthreads();
    if (tid < BM) {
        float m = fminf(fminf(rowred[tid], rowred[BM + tid]),
                        fminf(rowred[2 * BM + tid], rowred[3 * BM + tid]));
        float v = ((const float*)(smem + OFF_X2S))[tid] + m;
#pragma unroll
        for (int s = 16; s >= 1; s >>= 1) v += __shfl_xor_sync(0xffffffffu, v, s);
        if (lane == 0) ((float*)(smem + OFF_RED))[tid >> 5] = v;
    }
    __syncthreads();
    if (tid == 0) {
        const float* rd = (const float*)(smem + OFF_RED);
        g_partials[blockIdx.x] = rd[0] + rd[1] + rd[2] + rd[3];
    }
}

// ---------------------------------------------------------------------------
// Finalize: deterministic reduction + mean(psi), vectorized
// ---------------------------------------------------------------------------
__global__ void finalize_kernel(const float* __restrict__ psi,
                                float* __restrict__ out) {
    __shared__ float sh[256];
    int tid = threadIdx.x;
    float s = 0.f;
    for (int b = tid; b < NBLOCKS; b += 256) s += g_partials[b];
    s *= (1.0f / N_PTS);
    float p = 0.f;
    const float4* p4 = (const float4*)psi;
#pragma unroll
    for (int q = 0; q < M_PTS / 4 / 256; q++) {
        float4 v = p4[q * 256 + tid];
        p += (v.x + v.y) + (v.z + v.w);
    }
    s = fmaf(p, 1.0f / M_PTS, s);
    sh[tid] = s;
    __syncthreads();
    for (int off = 128; off > 0; off >>= 1) {
        if (tid < off) sh[tid] += sh[tid + off];
        __syncthreads();
    }
    if (tid == 0) out[0] = sh[0];
}

extern "C" void kernel_launch(void* const* d_in, const int* in_sizes, int n_in,
                              void* d_out, int out_size) {
    (void)in_sizes; (void)n_in; (void)out_size;
    const float* x   = (const float*)d_in[0];   // [N, D]
    const float* y   = (const float*)d_in[1];   // [M, D]
    const float* psi = (const float*)d_in[2];   // [M]
    float* out = (float*)d_out;

    cudaFuncSetAttribute(semidual_mma_kernel,
                         cudaFuncAttributeMaxDynamicSharedMemorySize, SMEM_TOTAL);

    prep_y_kernel<<<(M_PTS * D_DIM / 16) / 256, 256>>>(y, psi);
    semidual_mma_kernel<<<NBLOCKS, 256, SMEM_TOTAL>>>(x);
    finalize_kernel<<<1, 256>>>(psi, out);
}

// round 13
// speedup vs baseline: 2.6448x; 2.6448x over previous
#include <cuda_runtime.h>
#include <cuda_fp16.h>
#include <cstdint>

#define N_PTS 32768
#define M_PTS 8192
#define D_DIM 64
#define BM 128
#define BN 128
#define N_ITILES (N_PTS / BM)        // 256
#define N_YTILES (M_PTS / BN)        // 64
#define NU (N_ITILES * N_YTILES)     // 16384 work units
#define GRIDN 296                    // 148 SMs x occ 2

// dynamic smem layout (bytes)
#define OFF_XH     0                 // 16384
#define OFF_Y      16384             // 3 * 16384 (triple-buffered y)
#define OFF_BS     65536             // 3 * 128 * 4
#define OFF_X2S    67072             // 128 * 4
#define OFF_ROWRED 67584             // 4 * 128 * 4
#define SMEM_TOTAL 69632

__device__ __half g_yh[M_PTS * D_DIM];
__device__ float g_b[M_PTS];
__device__ unsigned g_rowmin[N_PTS];   // float-flip keys, min via atomicMin

__device__ __forceinline__ uint32_t smem_u32(const void* p) {
    uint32_t a;
    asm("{ .reg .u64 t; cvta.to.shared.u64 t, %1; cvt.u32.u64 %0, t; }" : "=r"(a) : "l"(p));
    return a;
}
__device__ __forceinline__ uint32_t h2_u32(__half2 h) {
    uint32_t u;
    *reinterpret_cast<__half2*>(&u) = h;
    return u;
}
// monotonic unsigned key: ascending floats -> ascending unsigned
__device__ __forceinline__ unsigned fkey(float f) {
    unsigned u = __float_as_uint(f);
    unsigned mask = (unsigned)(-(int)(u >> 31)) | 0x80000000u;
    return u ^ mask;
}
__device__ __forceinline__ float funkey(unsigned k) {
    return __uint_as_float((k & 0x80000000u) ? (k ^ 0x80000000u) : ~k);
}

#define CP_ASYNC16(s, g) \
    asm volatile("cp.async.cg.shared.global [%0], [%1], 16;" :: "r"(s), "l"(g))
#define CP_COMMIT()  asm volatile("cp.async.commit_group;" ::: "memory")
#define CP_WAIT(N)   asm volatile("cp.async.wait_group %0;" :: "n"(N) : "memory")

#define LDSM4(r, addr) \
    asm volatile("ldmatrix.sync.aligned.m8n8.x4.shared.b16 {%0,%1,%2,%3}, [%4];" \
                 : "=r"((r)[0]), "=r"((r)[1]), "=r"((r)[2]), "=r"((r)[3]) : "r"(addr))

#define MMA_F16(c, a, b0, b1) \
    asm volatile("mma.sync.aligned.m16n8k16.row.col.f32.f16.f16.f32 " \
                 "{%0,%1,%2,%3},{%4,%5,%6,%7},{%8,%9},{%0,%1,%2,%3};" \
                 : "+f"((c)[0]), "+f"((c)[1]), "+f"((c)[2]), "+f"((c)[3]) \
                 : "r"((a)[0]), "r"((a)[1]), "r"((a)[2]), "r"((a)[3]), "r"(b0), "r"(b1))

// ---------------------------------------------------------------------------
// Prep: fp16 y; b_j = ||y_j||^2 - psi_j (fp32, exact); init g_rowmin
// grid: 128 blocks x 256 = 32768 threads
// ---------------------------------------------------------------------------
__global__ void prep_y_kernel(const float* __restrict__ y,
                              const float* __restrict__ psi) {
    int t = blockIdx.x * blockDim.x + threadIdx.x;   // 0 .. 32767
    g_rowmin[t] = 0xFFFFFFFFu;
    {
        // convert 16 y floats -> fp16 (t indexes 16-element chunks)
        const float4* src = (const float4*)(y + (size_t)t * 16);
        uint4 o;
        float4 v0 = src[0], v1 = src[1], v2 = src[2], v3 = src[3];
        o.x = h2_u32(__halves2half2(__float2half(v0.x), __float2half(v0.y)));
        o.y = h2_u32(__halves2half2(__float2half(v0.z), __float2half(v0.w)));
        o.z = h2_u32(__halves2half2(__float2half(v1.x), __float2half(v1.y)));
        o.w = h2_u32(__halves2half2(__float2half(v1.z), __float2half(v1.w)));
        ((uint4*)g_yh)[t * 2] = o;
        o.x = h2_u32(__halves2half2(__float2half(v2.x), __float2half(v2.y)));
        o.y = h2_u32(__halves2half2(__float2half(v2.z), __float2half(v2.w)));
        o.z = h2_u32(__halves2half2(__float2half(v3.x), __float2half(v3.y)));
        o.w = h2_u32(__halves2half2(__float2half(v3.z), __float2half(v3.w)));
        ((uint4*)g_yh)[t * 2 + 1] = o;
    }
    if (t < M_PTS) {
        const float4* yr = (const float4*)(y + (size_t)t * D_DIM);
        float s = 0.f;
#pragma unroll
        for (int q = 0; q < 16; q++) {
            float4 w = yr[q];
            s = fmaf(w.x, w.x, s); s = fmaf(w.y, w.y, s);
            s = fmaf(w.z, w.z, s); s = fmaf(w.w, w.w, s);
        }
        g_b[t] = s - psi[t];
    }
}

// ---------------------------------------------------------------------------
// Main: balanced persistent grid of 296 CTAs over 16384 (i-tile, y-tile)
// units; fp16 mma (f32 acc), chunked accumulators; atomicMin row flush.
// ---------------------------------------------------------------------------
__global__ __launch_bounds__(256, 2)
void semidual_mma_kernel(const float* __restrict__ x) {
    extern __shared__ char smem[];
    const uint32_t sb = smem_u32(smem);
    const int tid  = threadIdx.x;
    const int lane = tid & 31;
    const int w    = tid >> 5;
    const int wm   = w >> 2;
    const int wn   = w & 3;

    const int us = (int)(((long long)blockIdx.x * NU) / GRIDN);
    const int ue = (int)(((long long)(blockIdx.x + 1) * NU) / GRIDN);

    // cp.async one [128 x 64] fp16 y-tile with swizzled stores
    auto tile_cp = [&](int row0, uint32_t soff) {
        const char* gp = (const char*)(g_yh + (size_t)row0 * D_DIM);
#pragma unroll
        for (int it = 0; it < 4; it++) {
            int c   = it * 256 + tid;        // 0..1023
            int row = c >> 3, col = c & 7;
            uint32_t so = sb + soff + row * 128 + ((col ^ (row & 7)) << 4);
            CP_ASYNC16(so, gp + (size_t)c * 16);
        }
    };

    // per-lane invariant addressing pieces
    const uint32_t aoff  = (uint32_t)(wm * 64 + (lane & 15)) * 128;
    const int      cselA = lane >> 4;
    const int      axorA = (lane & 7);
    const uint32_t boff  = (uint32_t)(wn * 32 + ((lane >> 4) << 3) + (lane & 7)) * 128;
    const int      cselB = (lane >> 3) & 1;
    const int      bxorB = (lane & 7);
    const int      j0b   = wn * 32 + (lane & 3) * 2;

    float rmin[8];
    float* rowred = (float*)(smem + OFF_ROWRED);

    // flush row minima of i-tile fit into global via atomicMin
    auto flush = [&](int fit) {
#pragma unroll
        for (int r = 0; r < 8; r++) {
            rmin[r] = fminf(rmin[r], __shfl_xor_sync(0xffffffffu, rmin[r], 1));
            rmin[r] = fminf(rmin[r], __shfl_xor_sync(0xffffffffu, rmin[r], 2));
        }
        __syncthreads();
        if ((lane & 3) == 0) {
            const int g = lane >> 2;
#pragma unroll
            for (int mt = 0; mt < 4; mt++) {
                const int r0 = wm * 64 + mt * 16 + g;
                rowred[wn * BM + r0]     = rmin[mt * 2];
                rowred[wn * BM + r0 + 8] = rmin[mt * 2 + 1];
            }
        }
        __syncthreads();
        if (tid < BM) {
            float m = fminf(fminf(rowred[tid], rowred[BM + tid]),
                            fminf(rowred[2 * BM + tid], rowred[3 * BM + tid]));
            float v = ((const float*)(smem + OFF_X2S))[tid] + m;
            atomicMin(&g_rowmin[fit * BM + tid], fkey(v));
        }
    };

    // prologue: y tile of first unit into slot 0
    tile_cp((us & 63) * BN, OFF_Y);
    CP_COMMIT();
    if (tid < BN) ((float*)(smem + OFF_BS))[tid] = g_b[(us & 63) * BN + tid];

    int cur_it = -1;

    for (int u = us; u < ue; u++) {
        const int li = u - us;
        const int b  = li % 3;
        const int it = u >> 6;

        if (it != cur_it) {
            if (cur_it >= 0) flush(cur_it);
            __syncthreads();   // all warps done with old XH/X2S
            // convert x tile fp32 -> fp16 into swizzled smem + x2
            const int i0 = it * BM;
            const float4* x4 = (const float4*)(x + (size_t)i0 * D_DIM);
#pragma unroll
            for (int itc = 0; itc < 4; itc++) {
                int c   = itc * 256 + tid;        // 0..1023
                int row = c >> 3, col8 = c & 7;
                float4 v0 = x4[row * 16 + col8 * 2];
                float4 v1 = x4[row * 16 + col8 * 2 + 1];
                uint4 h;
                h.x = h2_u32(__halves2half2(__float2half(v0.x), __float2half(v0.y)));
                h.y = h2_u32(__halves2half2(__float2half(v0.z), __float2half(v0.w)));
                h.z = h2_u32(__halves2half2(__float2half(v1.x), __float2half(v1.y)));
                h.w = h2_u32(__halves2half2(__float2half(v1.z), __float2half(v1.w)));
                *(uint4*)(smem + OFF_XH + row * 128 + ((col8 ^ (row & 7)) << 4)) = h;
            }
            if (tid < BM) {
                const float4* xr = (const float4*)(x + (size_t)(i0 + tid) * D_DIM);
                float x2 = 0.f;
#pragma unroll
                for (int q = 0; q < 16; q++) {
                    float4 v = xr[q];
                    x2 = fmaf(v.x, v.x, x2); x2 = fmaf(v.y, v.y, x2);
                    x2 = fmaf(v.z, v.z, x2); x2 = fmaf(v.w, v.w, x2);
                }
                ((float*)(smem + OFF_X2S))[tid] = x2;
            }
#pragma unroll
            for (int r = 0; r < 8; r++) rmin[r] = 3.4e38f;
            cur_it = it;
        }

        if (u + 1 < ue) {
            const int nb = (li + 1) % 3;
            tile_cp(((u + 1) & 63) * BN, OFF_Y + nb * 16384);
            CP_COMMIT();
            if (tid < BN)
                ((float*)(smem + OFF_BS))[nb * BN + tid] = g_b[((u + 1) & 63) * BN + tid];
            CP_WAIT(1);
        } else {
            CP_WAIT(0);
        }
        __syncthreads();

        const uint32_t yb  = sb + OFF_Y + b * 16384;
        const uint32_t axh = sb + OFF_XH;
        const float* bsf = (const float*)(smem + OFF_BS) + b * BN;

#pragma unroll
        for (int mtc = 0; mtc < 2; mtc++) {
            float c[2][4][4];
#pragma unroll
            for (int mt = 0; mt < 2; mt++)
#pragma unroll
                for (int nt = 0; nt < 4; nt++)
#pragma unroll
                    for (int q = 0; q < 4; q++) c[mt][nt][q] = 0.f;

#pragma unroll
            for (int kb = 0; kb < 4; kb++) {
                const uint32_t ca = (uint32_t)(((2 * kb + cselA) ^ axorA) << 4);
                const uint32_t cb = (uint32_t)(((2 * kb + cselB) ^ bxorB) << 4);
                uint32_t a[2][4], bb[2][4];
#pragma unroll
                for (int mt = 0; mt < 2; mt++)
                    LDSM4(a[mt], axh + aoff + (mtc * 2 + mt) * 2048 + ca);
#pragma unroll
                for (int np = 0; np < 2; np++)
                    LDSM4(bb[np], yb + boff + np * 2048 + cb);
#pragma unroll
                for (int mt = 0; mt < 2; mt++)
#pragma unroll
                    for (int nt = 0; nt < 4; nt++)
                        MMA_F16(c[mt][nt], a[mt], bb[nt >> 1][(nt & 1) * 2], bb[nt >> 1][(nt & 1) * 2 + 1]);
            }

#pragma unroll
            for (int nt = 0; nt < 4; nt++) {
                const float b0 = bsf[j0b + nt * 8];
                const float b1 = bsf[j0b + nt * 8 + 1];
#pragma unroll
                for (int mt = 0; mt < 2; mt++) {
                    const int mi = mtc * 2 + mt;
                    float v0 = fminf(fmaf(-2.f, c[mt][nt][0], b0), fmaf(-2.f, c[mt][nt][1], b1));
                    float v1 = fminf(fmaf(-2.f, c[mt][nt][2], b0), fmaf(-2.f, c[mt][nt][3], b1));
                    rmin[mi * 2]     = fminf(rmin[mi * 2], v0);
                    rmin[mi * 2 + 1] = fminf(rmin[mi * 2 + 1], v1);
                }
            }
        }
    }

    flush(cur_it);
}

// ---------------------------------------------------------------------------
// Finalize: decode row minima, deterministic sum + mean(psi)
// ---------------------------------------------------------------------------
__global__ void finalize_kernel(const float* __restrict__ psi,
                                float* __restrict__ out) {
    __shared__ float sh[256];
    int tid = threadIdx.x;
    float s = 0.f;
    for (int i = tid; i < N_PTS; i += 256)
        s += funkey(g_rowmin[i]);
    s *= (1.0f / N_PTS);
    float p = 0.f;
    const float4* p4 = (const float4*)psi;
#pragma unroll
    for (int q = 0; q < M_PTS / 4 / 256; q++) {
        float4 v = p4[q * 256 + tid];
        p += (v.x + v.y) + (v.z + v.w);
    }
    s = fmaf(p, 1.0f / M_PTS, s);
    sh[tid] = s;
    __syncthreads();
    for (int off = 128; off > 0; off >>= 1) {
        if (tid < off) sh[tid] += sh[tid + off];
        __syncthreads();
    }
    if (tid == 0) out[0] = sh[0];
}

extern "C" void kernel_launch(void* const* d_in, const int* in_sizes, int n_in,
                              void* d_out, int out_size) {
    (void)in_sizes; (void)n_in; (void)out_size;
    const float* x   = (const float*)d_in[0];   // [N, D]
    const float* y   = (const float*)d_in[1];   // [M, D]
    const float* psi = (const float*)d_in[2];   // [M]
    float* out = (float*)d_out;

    cudaFuncSetAttribute(semidual_mma_kernel,
                         cudaFuncAttributeMaxDynamicSharedMemorySize, SMEM_TOTAL);

    prep_y_kernel<<<(M_PTS * D_DIM / 16) / 256, 256>>>(y, psi);
    semidual_mma_kernel<<<GRIDN, 256, SMEM_TOTAL>>>(x);
    finalize_kernel<<<1, 256>>>(psi, out);
}